// round 1
// baseline (speedup 1.0000x reference)
#include <cuda_runtime.h>
#include <math.h>

#define D_MODEL 1024
#define D_FF    2048
#define NE      8
#define CAP     4096   // max tokens per expert (top-2 => each expert <= T)
#define MAXT    4096

// ---- device scratch (no cudaMalloc allowed) ----
__device__ float g_H[2 * MAXT * D_FF];   // 64 MB: gelu(x@W1+b1) rows, compacted by expert
__device__ int   g_tok[NE * CAP];        // gathered token index per (expert, slot)
__device__ float g_wt[NE * CAP];         // routing weight per (expert, slot)
__device__ int   g_cnt[NE];
__device__ int   g_off[NE];
__device__ float g_imp[NE];              // sum of softmax probs per expert

// ---------------------------------------------------------------------------
__global__ void zero_kernel(float* out, int n) {
    int i = blockIdx.x * blockDim.x + threadIdx.x;
    if (i < n) out[i] = 0.0f;
    if (blockIdx.x == 0 && threadIdx.x < NE) {
        g_cnt[threadIdx.x] = 0;
        g_imp[threadIdx.x] = 0.0f;
    }
}

// ---------------------------------------------------------------------------
// One block (256 thr) per token: logits[8] = x_t @ router_w + b, softmax, top-2.
__global__ void router_kernel(const float* __restrict__ x,
                              const float* __restrict__ rw,
                              const float* __restrict__ rb) {
    const int t   = blockIdx.x;
    const int tid = threadIdx.x;

    float part[NE];
#pragma unroll
    for (int e = 0; e < NE; e++) part[e] = 0.0f;

    const float* xr = x + (size_t)t * D_MODEL;
    for (int d = tid; d < D_MODEL; d += 256) {
        float xv = xr[d];
        const float4* w4 = (const float4*)(rw + (size_t)d * NE);
        float4 w0 = w4[0], w1 = w4[1];
        part[0] += xv * w0.x; part[1] += xv * w0.y;
        part[2] += xv * w0.z; part[3] += xv * w0.w;
        part[4] += xv * w1.x; part[5] += xv * w1.y;
        part[6] += xv * w1.z; part[7] += xv * w1.w;
    }

#pragma unroll
    for (int e = 0; e < NE; e++)
#pragma unroll
        for (int o = 16; o > 0; o >>= 1)
            part[e] += __shfl_down_sync(0xffffffffu, part[e], o);

    __shared__ float sred[8][NE];
    const int wid = tid >> 5, lid = tid & 31;
    if (lid == 0)
#pragma unroll
        for (int e = 0; e < NE; e++) sred[wid][e] = part[e];
    __syncthreads();

    if (tid == 0) {
        float lg[NE];
#pragma unroll
        for (int e = 0; e < NE; e++) {
            float s = rb[e];
#pragma unroll
            for (int w = 0; w < 8; w++) s += sred[w][e];
            lg[e] = s;
        }
        float m = lg[0];
#pragma unroll
        for (int e = 1; e < NE; e++) m = fmaxf(m, lg[e]);
        float p[NE], s = 0.0f;
#pragma unroll
        for (int e = 0; e < NE; e++) { p[e] = expf(lg[e] - m); s += p[e]; }
        float inv = 1.0f / s;
#pragma unroll
        for (int e = 0; e < NE; e++) {
            p[e] *= inv;
            atomicAdd(&g_imp[e], p[e]);
        }
        // top-2 (stable: earliest index wins ties, like jax top_k)
        int i0 = 0;
#pragma unroll
        for (int e = 1; e < NE; e++) if (p[e] > p[i0]) i0 = e;
        int i1 = (i0 == 0) ? 1 : 0;
#pragma unroll
        for (int e = 0; e < NE; e++) if (e != i0 && p[e] > p[i1]) i1 = e;

        float ps = fmaxf(p[i0] + p[i1], 1e-9f);
        float w0 = p[i0] / ps, w1 = p[i1] / ps;

        int s0 = atomicAdd(&g_cnt[i0], 1);
        g_tok[i0 * CAP + s0] = t; g_wt[i0 * CAP + s0] = w0;
        int s1 = atomicAdd(&g_cnt[i1], 1);
        g_tok[i1 * CAP + s1] = t; g_wt[i1 * CAP + s1] = w1;
    }
}

// ---------------------------------------------------------------------------
__global__ void finalize_kernel(float* out, int T, long long out_size) {
    if (blockIdx.x == 0 && threadIdx.x == 0) {
        int off = 0;
        for (int e = 0; e < NE; e++) { g_off[e] = off; off += g_cnt[e]; }
        float aux = 0.0f;
        for (int e = 0; e < NE; e++)
            aux += (g_imp[e] / (float)T) * ((float)g_cnt[e] / (float)(T * 2));
        aux *= (float)NE;
        long long oi = (long long)T * D_MODEL;
        if (oi < out_size) out[oi] = aux;
    }
}

// ---------------------------------------------------------------------------
// GEMM1: H[off[e]+m, :] = gelu(x[tok] @ W1[e] + b1[e]).  64x64x16 tiles.
__global__ void __launch_bounds__(256) gemm1_kernel(const float* __restrict__ x,
                                                    const float* __restrict__ W1,
                                                    const float* __restrict__ b1) {
    const int e   = blockIdx.z;
    const int cnt = g_cnt[e];
    const int m0  = blockIdx.y * 64;
    if (m0 >= cnt) return;
    const int n0  = blockIdx.x * 64;

    __shared__ float As[16][64];
    __shared__ float Bs[16][64];
    __shared__ int   stok[64];

    const int tid = threadIdx.x;
    if (tid < 64) {
        int m = min(m0 + tid, cnt - 1);
        stok[tid] = g_tok[e * CAP + m];
    }
    __syncthreads();

    const int arow = tid >> 2;          // 0..63
    const int acol = (tid & 3) * 4;     // 0,4,8,12
    const int brow = tid >> 4;          // 0..15
    const int bcol = (tid & 15) * 4;    // 0..60
    const int ty   = tid >> 4;          // 0..15
    const int tx   = tid & 15;          // 0..15

    const float* Aptr  = x + (size_t)stok[arow] * D_MODEL + acol;
    const float* Bbase = W1 + (size_t)e * D_MODEL * D_FF + n0 + bcol;

    float acc[4][4] = {};

    for (int k0 = 0; k0 < D_MODEL; k0 += 16) {
        float4 av = *(const float4*)(Aptr + k0);
        float4 bv = *(const float4*)(Bbase + (size_t)(k0 + brow) * D_FF);
        As[acol + 0][arow] = av.x; As[acol + 1][arow] = av.y;
        As[acol + 2][arow] = av.z; As[acol + 3][arow] = av.w;
        *(float4*)&Bs[brow][bcol] = bv;
        __syncthreads();
#pragma unroll
        for (int k = 0; k < 16; k++) {
            float4 a = *(const float4*)&As[k][ty * 4];
            float4 b = *(const float4*)&Bs[k][tx * 4];
            acc[0][0] += a.x * b.x; acc[0][1] += a.x * b.y; acc[0][2] += a.x * b.z; acc[0][3] += a.x * b.w;
            acc[1][0] += a.y * b.x; acc[1][1] += a.y * b.y; acc[1][2] += a.y * b.z; acc[1][3] += a.y * b.w;
            acc[2][0] += a.z * b.x; acc[2][1] += a.z * b.y; acc[2][2] += a.z * b.z; acc[2][3] += a.z * b.w;
            acc[3][0] += a.w * b.x; acc[3][1] += a.w * b.y; acc[3][2] += a.w * b.z; acc[3][3] += a.w * b.w;
        }
        __syncthreads();
    }

    const int base = g_off[e];
#pragma unroll
    for (int i = 0; i < 4; i++) {
        int m = m0 + ty * 4 + i;
        if (m < cnt) {
            float* hrow = g_H + (size_t)(base + m) * D_FF + n0 + tx * 4;
#pragma unroll
            for (int j = 0; j < 4; j++) {
                float h = acc[i][j] + b1[e * D_FF + n0 + tx * 4 + j];
                h = 0.5f * h * (1.0f + erff(h * 0.70710678118654752f));  // exact GELU
                hrow[j] = h;
            }
        }
    }
}

// ---------------------------------------------------------------------------
// GEMM2: out[tok, :] += w * (H[row] @ W2[e] + b2[e]).  64x64x16 tiles.
__global__ void __launch_bounds__(256) gemm2_kernel(const float* __restrict__ W2,
                                                    const float* __restrict__ b2,
                                                    float* __restrict__ out) {
    const int e   = blockIdx.z;
    const int cnt = g_cnt[e];
    const int m0  = blockIdx.y * 64;
    if (m0 >= cnt) return;
    const int n0  = blockIdx.x * 64;

    __shared__ float As[16][64];
    __shared__ float Bs[16][64];
    __shared__ int   stok[64];
    __shared__ float sw[64];

    const int tid = threadIdx.x;
    if (tid < 64) {
        int m = min(m0 + tid, cnt - 1);
        stok[tid] = g_tok[e * CAP + m];
        sw[tid]   = g_wt[e * CAP + m];
    }
    __syncthreads();

    const int arow = tid >> 2;
    const int acol = (tid & 3) * 4;
    const int brow = tid >> 4;
    const int bcol = (tid & 15) * 4;
    const int ty   = tid >> 4;
    const int tx   = tid & 15;

    const int base = g_off[e];
    const int mrow = min(m0 + arow, cnt - 1);
    const float* Aptr  = g_H + (size_t)(base + mrow) * D_FF + acol;
    const float* Bbase = W2 + (size_t)e * D_FF * D_MODEL + n0 + bcol;

    float acc[4][4] = {};

    for (int k0 = 0; k0 < D_FF; k0 += 16) {
        float4 av = *(const float4*)(Aptr + k0);
        float4 bv = *(const float4*)(Bbase + (size_t)(k0 + brow) * D_MODEL);
        As[acol + 0][arow] = av.x; As[acol + 1][arow] = av.y;
        As[acol + 2][arow] = av.z; As[acol + 3][arow] = av.w;
        *(float4*)&Bs[brow][bcol] = bv;
        __syncthreads();
#pragma unroll
        for (int k = 0; k < 16; k++) {
            float4 a = *(const float4*)&As[k][ty * 4];
            float4 b = *(const float4*)&Bs[k][tx * 4];
            acc[0][0] += a.x * b.x; acc[0][1] += a.x * b.y; acc[0][2] += a.x * b.z; acc[0][3] += a.x * b.w;
            acc[1][0] += a.y * b.x; acc[1][1] += a.y * b.y; acc[1][2] += a.y * b.z; acc[1][3] += a.y * b.w;
            acc[2][0] += a.z * b.x; acc[2][1] += a.z * b.y; acc[2][2] += a.z * b.z; acc[2][3] += a.z * b.w;
            acc[3][0] += a.w * b.x; acc[3][1] += a.w * b.y; acc[3][2] += a.w * b.z; acc[3][3] += a.w * b.w;
        }
        __syncthreads();
    }

#pragma unroll
    for (int i = 0; i < 4; i++) {
        int lm = ty * 4 + i;
        int m  = m0 + lm;
        if (m < cnt) {
            int   tok = stok[lm];
            float w   = sw[lm];
            float* orow = out + (size_t)tok * D_MODEL + n0 + tx * 4;
#pragma unroll
            for (int j = 0; j < 4; j++) {
                float y = acc[i][j] + b2[e * D_MODEL + n0 + tx * 4 + j];
                atomicAdd(&orow[j], w * y);   // exactly 2 adds per element -> deterministic
            }
        }
    }
}

// ---------------------------------------------------------------------------
extern "C" void kernel_launch(void* const* d_in, const int* in_sizes, int n_in,
                              void* d_out, int out_size) {
    const float* x  = (const float*)d_in[0];
    const float* rw = (const float*)d_in[1];
    const float* rb = (const float*)d_in[2];
    const float* W1 = (const float*)d_in[3];
    const float* b1 = (const float*)d_in[4];
    const float* W2 = (const float*)d_in[5];
    const float* b2 = (const float*)d_in[6];
    float* out = (float*)d_out;

    const int T = in_sizes[0] / D_MODEL;   // 4096

    zero_kernel<<<(out_size + 255) / 256, 256>>>(out, out_size);
    router_kernel<<<T, 256>>>(x, rw, rb);
    finalize_kernel<<<1, 1>>>(out, T, (long long)out_size);

    dim3 g1(D_FF / 64, (T + 63) / 64, NE);
    gemm1_kernel<<<g1, 256>>>(x, W1, b1);

    dim3 g2(D_MODEL / 64, (T + 63) / 64, NE);
    gemm2_kernel<<<g2, 256>>>(W2, b2, out);
}

// round 4
// speedup vs baseline: 1.4661x; 1.4661x over previous
#include <cuda_runtime.h>
#include <cstdint>
#include <math.h>

#define D_MODEL 1024
#define D_FF    2048
#define NE      8
#define CAP     4096
#define MAXT    4096

// ---- device scratch ----
__device__ float g_H[2 * MAXT * D_FF];   // 64 MB
__device__ int   g_tok[NE * CAP];
__device__ float g_wt[NE * CAP];
__device__ int   g_cnt[NE];
__device__ int   g_off[NE];
__device__ float g_imp[NE];

// ======================= portable PTX helpers ==============================
__device__ __forceinline__ uint32_t smem_u32(const void* p) {
    uint32_t a;
    asm("{ .reg .u64 t; cvta.to.shared.u64 t, %1; cvt.u32.u64 %0, t; }" : "=r"(a) : "l"(p));
    return a;
}
__device__ __forceinline__ void cp16(uint32_t smem, const void* g) {
    asm volatile("cp.async.cg.shared.global [%0], [%1], 16;" :: "r"(smem), "l"(g));
}
#define CP_COMMIT() asm volatile("cp.async.commit_group;" ::: "memory")
#define CP_WAIT(n)  asm volatile("cp.async.wait_group %0;" :: "n"(n) : "memory")

__device__ __forceinline__ void mma_tf32(float* c,
                                         uint32_t a0, uint32_t a1, uint32_t a2, uint32_t a3,
                                         uint32_t b0, uint32_t b1) {
    asm volatile(
        "mma.sync.aligned.m16n8k8.row.col.f32.tf32.tf32.f32 "
        "{%0,%1,%2,%3}, {%4,%5,%6,%7}, {%8,%9}, {%0,%1,%2,%3};"
        : "+f"(c[0]), "+f"(c[1]), "+f"(c[2]), "+f"(c[3])
        : "r"(a0), "r"(a1), "r"(a2), "r"(a3), "r"(b0), "r"(b1));
}
// 3xTF32 split: hi = tf32(v), lo = tf32(v - hi)
__device__ __forceinline__ void tf32_split(float v, uint32_t& hi, uint32_t& lo) {
    asm("cvt.rna.tf32.f32 %0, %1;" : "=r"(hi) : "f"(v));
    float l = v - __uint_as_float(hi);
    asm("cvt.rna.tf32.f32 %0, %1;" : "=r"(lo) : "f"(l));
}

// ======================= small kernels =====================================
__global__ void zero_kernel(float* out, int n) {
    int i = blockIdx.x * blockDim.x + threadIdx.x;
    if (i < n) out[i] = 0.0f;
    if (blockIdx.x == 0 && threadIdx.x < NE) { g_cnt[threadIdx.x] = 0; g_imp[threadIdx.x] = 0.0f; }
}

__global__ void router_kernel(const float* __restrict__ x,
                              const float* __restrict__ rw,
                              const float* __restrict__ rb) {
    const int t = blockIdx.x, tid = threadIdx.x;
    float part[NE];
#pragma unroll
    for (int e = 0; e < NE; e++) part[e] = 0.0f;
    const float* xr = x + (size_t)t * D_MODEL;
    for (int d = tid; d < D_MODEL; d += 256) {
        float xv = xr[d];
        const float4* w4 = (const float4*)(rw + (size_t)d * NE);
        float4 w0 = w4[0], w1 = w4[1];
        part[0] += xv * w0.x; part[1] += xv * w0.y; part[2] += xv * w0.z; part[3] += xv * w0.w;
        part[4] += xv * w1.x; part[5] += xv * w1.y; part[6] += xv * w1.z; part[7] += xv * w1.w;
    }
#pragma unroll
    for (int e = 0; e < NE; e++)
#pragma unroll
        for (int o = 16; o > 0; o >>= 1) part[e] += __shfl_down_sync(0xffffffffu, part[e], o);
    __shared__ float sred[8][NE];
    const int wid = tid >> 5, lid = tid & 31;
    if (lid == 0)
#pragma unroll
        for (int e = 0; e < NE; e++) sred[wid][e] = part[e];
    __syncthreads();
    if (tid == 0) {
        float lg[NE];
#pragma unroll
        for (int e = 0; e < NE; e++) {
            float s = rb[e];
#pragma unroll
            for (int w = 0; w < 8; w++) s += sred[w][e];
            lg[e] = s;
        }
        float m = lg[0];
#pragma unroll
        for (int e = 1; e < NE; e++) m = fmaxf(m, lg[e]);
        float p[NE], s = 0.0f;
#pragma unroll
        for (int e = 0; e < NE; e++) { p[e] = expf(lg[e] - m); s += p[e]; }
        float inv = 1.0f / s;
#pragma unroll
        for (int e = 0; e < NE; e++) { p[e] *= inv; atomicAdd(&g_imp[e], p[e]); }
        int i0 = 0;
#pragma unroll
        for (int e = 1; e < NE; e++) if (p[e] > p[i0]) i0 = e;
        int i1 = (i0 == 0) ? 1 : 0;
#pragma unroll
        for (int e = 0; e < NE; e++) if (e != i0 && p[e] > p[i1]) i1 = e;
        float ps = fmaxf(p[i0] + p[i1], 1e-9f);
        int s0 = atomicAdd(&g_cnt[i0], 1);
        g_tok[i0 * CAP + s0] = t; g_wt[i0 * CAP + s0] = p[i0] / ps;
        int s1 = atomicAdd(&g_cnt[i1], 1);
        g_tok[i1 * CAP + s1] = t; g_wt[i1 * CAP + s1] = p[i1] / ps;
    }
}

__global__ void finalize_kernel(float* out, int T, long long out_size) {
    if (threadIdx.x == 0) {
        int off = 0;
        for (int e = 0; e < NE; e++) { g_off[e] = off; off += g_cnt[e]; }
        float aux = 0.0f;
        for (int e = 0; e < NE; e++)
            aux += (g_imp[e] / (float)T) * ((float)g_cnt[e] / (float)(T * 2));
        aux *= (float)NE;
        long long oi = (long long)T * D_MODEL;
        if (oi < out_size) out[oi] = aux;
    }
}

// ======================= 3xTF32 mma.sync grouped GEMMs =====================
// CTA tile 128(M) x 128(N), K-chunk 16, double-buffered cp.async.
#define AST 20
#define BST 136

struct __align__(16) SmemMMA {
    float A[2][128 * AST];
    float B[2][16 * BST];
    int   stok[128];
    float swt[128];
};

template<int LDK>
__device__ __forceinline__ void load_chunk(SmemMMA& sm, int buf, int k0,
                                           const float* __restrict__ src_rows_base,
                                           const int* __restrict__ srow,
                                           const float* __restrict__ Wb, int WLD, int n0,
                                           int tid) {
    uint32_t aBase = smem_u32(sm.A[buf]);
    uint32_t bBase = smem_u32(sm.B[buf]);
#pragma unroll
    for (int it = 0; it < 2; it++) {
        int i = tid + it * 256;
        int row = i >> 2, c = i & 3;
        const float* g = src_rows_base + (size_t)srow[row] * LDK + k0 + c * 4;
        cp16(aBase + (row * AST + c * 4) * 4, g);
    }
#pragma unroll
    for (int it = 0; it < 2; it++) {
        int i = tid + it * 256;
        int kr = i >> 5, f4 = i & 31;
        const float* g = Wb + (size_t)(k0 + kr) * WLD + n0 + f4 * 4;
        cp16(bBase + (kr * BST + f4 * 4) * 4, g);
    }
}

// compute one K-chunk (2 k8 steps), 3xTF32 compensated
__device__ __forceinline__ void compute_chunk(const SmemMMA& sm, int buf,
                                              int warp_m, int warp_n, int g, int tig,
                                              float acc[2][8][4]) {
    const float* Ab = sm.A[buf];
    const float* Bb = sm.B[buf];
#pragma unroll
    for (int s = 0; s < 2; s++) {
        uint32_t ah[2][4], al[2][4];
#pragma unroll
        for (int mt = 0; mt < 2; mt++) {
            const float* p = Ab + (warp_m + mt * 16 + g) * AST + s * 8 + tig;
            tf32_split(p[0],            ah[mt][0], al[mt][0]);
            tf32_split(p[8 * AST],      ah[mt][1], al[mt][1]);
            tf32_split(p[4],            ah[mt][2], al[mt][2]);
            tf32_split(p[8 * AST + 4],  ah[mt][3], al[mt][3]);
        }
        uint32_t bh[8][2], bl[8][2];
#pragma unroll
        for (int nt = 0; nt < 8; nt++) {
            const float* p = Bb + (s * 8 + tig) * BST + warp_n + nt * 8 + g;
            tf32_split(p[0],        bh[nt][0], bl[nt][0]);
            tf32_split(p[4 * BST],  bh[nt][1], bl[nt][1]);
        }
#pragma unroll
        for (int mt = 0; mt < 2; mt++)
#pragma unroll
            for (int nt = 0; nt < 8; nt++) {
                mma_tf32(acc[mt][nt], ah[mt][0], ah[mt][1], ah[mt][2], ah[mt][3],
                         bl[nt][0], bl[nt][1]);
                mma_tf32(acc[mt][nt], al[mt][0], al[mt][1], al[mt][2], al[mt][3],
                         bh[nt][0], bh[nt][1]);
                mma_tf32(acc[mt][nt], ah[mt][0], ah[mt][1], ah[mt][2], ah[mt][3],
                         bh[nt][0], bh[nt][1]);
            }
    }
}

// GEMM1: H[off+m, n] = gelu(x[tok_m] . W1[e][:, n] + b1[e][n])
__global__ void __launch_bounds__(256) gemm1_mma(const float* __restrict__ x,
                                                 const float* __restrict__ W1,
                                                 const float* __restrict__ b1) {
    __shared__ SmemMMA sm;
    const int e = blockIdx.z;
    const int cnt = g_cnt[e];
    const int m0 = blockIdx.y * 128;
    if (m0 >= cnt) return;
    const int n0 = blockIdx.x * 128;
    const int tid = threadIdx.x;
    const int wid = tid >> 5, lid = tid & 31;
    const int g = lid >> 2, tig = lid & 3;
    const int warp_m = (wid & 3) * 32, warp_n = (wid >> 2) * 64;

    if (tid < 128) sm.stok[tid] = g_tok[e * CAP + min(m0 + tid, cnt - 1)];
    __syncthreads();

    const float* Wb = W1 + (size_t)e * D_MODEL * D_FF;
    float acc[2][8][4];
#pragma unroll
    for (int a = 0; a < 2; a++)
#pragma unroll
        for (int b = 0; b < 8; b++)
#pragma unroll
            for (int c = 0; c < 4; c++) acc[a][b][c] = 0.0f;

    const int NC = D_MODEL / 16;  // 64
    load_chunk<D_MODEL>(sm, 0, 0, x, sm.stok, Wb, D_FF, n0, tid);
    CP_COMMIT();
    for (int c = 0; c < NC; c++) {
        if (c + 1 < NC) {
            load_chunk<D_MODEL>(sm, (c + 1) & 1, (c + 1) * 16, x, sm.stok, Wb, D_FF, n0, tid);
            CP_COMMIT();
            CP_WAIT(1);
        } else {
            CP_WAIT(0);
        }
        __syncthreads();
        compute_chunk(sm, c & 1, warp_m, warp_n, g, tig, acc);
        __syncthreads();
    }

    const int base = g_off[e];
#pragma unroll
    for (int mt = 0; mt < 2; mt++) {
#pragma unroll
        for (int half = 0; half < 2; half++) {
            int m = m0 + warp_m + mt * 16 + g + half * 8;
            if (m < cnt) {
                float* hrow = g_H + (size_t)(base + m) * D_FF;
#pragma unroll
                for (int nt = 0; nt < 8; nt++) {
                    int col = n0 + warp_n + nt * 8 + 2 * tig;
                    float v0 = acc[mt][nt][half * 2 + 0] + b1[e * D_FF + col];
                    float v1 = acc[mt][nt][half * 2 + 1] + b1[e * D_FF + col + 1];
                    float2 o;
                    o.x = 0.5f * v0 * (1.0f + erff(v0 * 0.70710678118654752f));
                    o.y = 0.5f * v1 * (1.0f + erff(v1 * 0.70710678118654752f));
                    *(float2*)(hrow + col) = o;
                }
            }
        }
    }
}

// GEMM2: out[tok_m, n] += w_m * (H[base+m, :] . W2[e][:, n] + b2[e][n])
__global__ void __launch_bounds__(256) gemm2_mma(const float* __restrict__ W2,
                                                 const float* __restrict__ b2,
                                                 float* __restrict__ out) {
    __shared__ SmemMMA sm;
    __shared__ int srow[128];
    const int e = blockIdx.z;
    const int cnt = g_cnt[e];
    const int m0 = blockIdx.y * 128;
    if (m0 >= cnt) return;
    const int n0 = blockIdx.x * 128;
    const int tid = threadIdx.x;
    const int wid = tid >> 5, lid = tid & 31;
    const int g = lid >> 2, tig = lid & 3;
    const int warp_m = (wid & 3) * 32, warp_n = (wid >> 2) * 64;
    const int base = g_off[e];

    if (tid < 128) {
        int m = min(m0 + tid, cnt - 1);
        sm.stok[tid] = g_tok[e * CAP + m];
        sm.swt[tid]  = g_wt[e * CAP + m];
        srow[tid]    = base + m;
    }
    __syncthreads();

    const float* Wb = W2 + (size_t)e * D_FF * D_MODEL;
    float acc[2][8][4];
#pragma unroll
    for (int a = 0; a < 2; a++)
#pragma unroll
        for (int b = 0; b < 8; b++)
#pragma unroll
            for (int c = 0; c < 4; c++) acc[a][b][c] = 0.0f;

    const int NC = D_FF / 16;  // 128
    load_chunk<D_FF>(sm, 0, 0, g_H, srow, Wb, D_MODEL, n0, tid);
    CP_COMMIT();
    for (int c = 0; c < NC; c++) {
        if (c + 1 < NC) {
            load_chunk<D_FF>(sm, (c + 1) & 1, (c + 1) * 16, g_H, srow, Wb, D_MODEL, n0, tid);
            CP_COMMIT();
            CP_WAIT(1);
        } else {
            CP_WAIT(0);
        }
        __syncthreads();
        compute_chunk(sm, c & 1, warp_m, warp_n, g, tig, acc);
        __syncthreads();
    }

#pragma unroll
    for (int mt = 0; mt < 2; mt++) {
#pragma unroll
        for (int half = 0; half < 2; half++) {
            int ml = warp_m + mt * 16 + g + half * 8;
            int m = m0 + ml;
            if (m < cnt) {
                int tok = sm.stok[ml];
                float w = sm.swt[ml];
                float* orow = out + (size_t)tok * D_MODEL;
#pragma unroll
                for (int nt = 0; nt < 8; nt++) {
                    int col = n0 + warp_n + nt * 8 + 2 * tig;
                    float y0 = acc[mt][nt][half * 2 + 0] + b2[e * D_MODEL + col];
                    float y1 = acc[mt][nt][half * 2 + 1] + b2[e * D_MODEL + col + 1];
                    atomicAdd(&orow[col], w * y0);
                    atomicAdd(&orow[col + 1], w * y1);
                }
            }
        }
    }
}

// ===========================================================================
extern "C" void kernel_launch(void* const* d_in, const int* in_sizes, int n_in,
                              void* d_out, int out_size) {
    const float* x  = (const float*)d_in[0];
    const float* rw = (const float*)d_in[1];
    const float* rb = (const float*)d_in[2];
    const float* W1 = (const float*)d_in[3];
    const float* b1 = (const float*)d_in[4];
    const float* W2 = (const float*)d_in[5];
    const float* b2 = (const float*)d_in[6];
    float* out = (float*)d_out;

    const int T = in_sizes[0] / D_MODEL;

    zero_kernel<<<(out_size + 255) / 256, 256>>>(out, out_size);
    router_kernel<<<T, 256>>>(x, rw, rb);
    finalize_kernel<<<1, 1>>>(out, T, (long long)out_size);

    dim3 g1(D_FF / 128, (T + 127) / 128, NE);
    gemm1_mma<<<g1, 256>>>(x, W1, b1);

    dim3 g2(D_MODEL / 128, (T + 127) / 128, NE);
    gemm2_mma<<<g2, 256>>>(W2, b2, out);
}

// round 7
// speedup vs baseline: 2.3982x; 1.6358x over previous
#include <cuda_runtime.h>
#include <cuda_fp16.h>
#include <cstdint>
#include <math.h>

#define D_MODEL 1024
#define D_FF    2048
#define NE      8
#define CAP     4096
#define MAXT    4096

// ---- device scratch ----
__device__ float g_H[2 * MAXT * D_FF];   // 64 MB
__device__ int   g_tok[NE * CAP];
__device__ float g_wt[NE * CAP];
__device__ int   g_cnt[NE];
__device__ int   g_off[NE];
__device__ float g_imp[NE];

// ======================= portable PTX helpers ==============================
__device__ __forceinline__ uint32_t smem_u32(const void* p) {
    uint32_t a;
    asm("{ .reg .u64 t; cvta.to.shared.u64 t, %1; cvt.u32.u64 %0, t; }" : "=r"(a) : "l"(p));
    return a;
}
__device__ __forceinline__ void cp16(uint32_t smem, const void* g) {
    asm volatile("cp.async.cg.shared.global [%0], [%1], 16;" :: "r"(smem), "l"(g));
}
#define CP_COMMIT() asm volatile("cp.async.commit_group;" ::: "memory")
#define CP_WAIT(n)  asm volatile("cp.async.wait_group %0;" :: "n"(n) : "memory")

__device__ __forceinline__ void mma_f16(float* c,
                                        uint32_t a0, uint32_t a1, uint32_t a2, uint32_t a3,
                                        uint32_t b0, uint32_t b1) {
    asm volatile(
        "mma.sync.aligned.m16n8k16.row.col.f32.f16.f16.f32 "
        "{%0,%1,%2,%3}, {%4,%5,%6,%7}, {%8,%9}, {%0,%1,%2,%3};"
        : "+f"(c[0]), "+f"(c[1]), "+f"(c[2]), "+f"(c[3])
        : "r"(a0), "r"(a1), "r"(a2), "r"(a3), "r"(b0), "r"(b1));
}

// fp16 2-way split of a float pair, packed into hi/lo __half2 bit-patterns
__device__ __forceinline__ void split2(float v0, float v1, uint32_t& hi, uint32_t& lo) {
    __half2 h2 = __floats2half2_rn(v0, v1);
    float2 hf = __half22float2(h2);
    __half2 l2 = __floats2half2_rn(v0 - hf.x, v1 - hf.y);
    hi = *reinterpret_cast<uint32_t*>(&h2);
    lo = *reinterpret_cast<uint32_t*>(&l2);
}

// ======================= small kernels =====================================
__global__ void zero_kernel(float* out, int n) {
    int i = blockIdx.x * blockDim.x + threadIdx.x;
    if (i < n) out[i] = 0.0f;
    if (blockIdx.x == 0 && threadIdx.x < NE) { g_cnt[threadIdx.x] = 0; g_imp[threadIdx.x] = 0.0f; }
}

__global__ void router_kernel(const float* __restrict__ x,
                              const float* __restrict__ rw,
                              const float* __restrict__ rb) {
    const int t = blockIdx.x, tid = threadIdx.x;
    float part[NE];
#pragma unroll
    for (int e = 0; e < NE; e++) part[e] = 0.0f;
    const float* xr = x + (size_t)t * D_MODEL;
    for (int d = tid; d < D_MODEL; d += 256) {
        float xv = xr[d];
        const float4* w4 = (const float4*)(rw + (size_t)d * NE);
        float4 w0 = w4[0], w1 = w4[1];
        part[0] += xv * w0.x; part[1] += xv * w0.y; part[2] += xv * w0.z; part[3] += xv * w0.w;
        part[4] += xv * w1.x; part[5] += xv * w1.y; part[6] += xv * w1.z; part[7] += xv * w1.w;
    }
#pragma unroll
    for (int e = 0; e < NE; e++)
#pragma unroll
        for (int o = 16; o > 0; o >>= 1) part[e] += __shfl_down_sync(0xffffffffu, part[e], o);
    __shared__ float sred[8][NE];
    const int wid = tid >> 5, lid = tid & 31;
    if (lid == 0)
#pragma unroll
        for (int e = 0; e < NE; e++) sred[wid][e] = part[e];
    __syncthreads();
    if (tid == 0) {
        float lg[NE];
#pragma unroll
        for (int e = 0; e < NE; e++) {
            float s = rb[e];
#pragma unroll
            for (int w = 0; w < 8; w++) s += sred[w][e];
            lg[e] = s;
        }
        float m = lg[0];
#pragma unroll
        for (int e = 1; e < NE; e++) m = fmaxf(m, lg[e]);
        float p[NE], s = 0.0f;
#pragma unroll
        for (int e = 0; e < NE; e++) { p[e] = expf(lg[e] - m); s += p[e]; }
        float inv = 1.0f / s;
#pragma unroll
        for (int e = 0; e < NE; e++) { p[e] *= inv; atomicAdd(&g_imp[e], p[e]); }
        int i0 = 0;
#pragma unroll
        for (int e = 1; e < NE; e++) if (p[e] > p[i0]) i0 = e;
        int i1 = (i0 == 0) ? 1 : 0;
#pragma unroll
        for (int e = 0; e < NE; e++) if (e != i0 && p[e] > p[i1]) i1 = e;
        float ps = fmaxf(p[i0] + p[i1], 1e-9f);
        int s0 = atomicAdd(&g_cnt[i0], 1);
        g_tok[i0 * CAP + s0] = t; g_wt[i0 * CAP + s0] = p[i0] / ps;
        int s1 = atomicAdd(&g_cnt[i1], 1);
        g_tok[i1 * CAP + s1] = t; g_wt[i1 * CAP + s1] = p[i1] / ps;
    }
}

__global__ void finalize_kernel(float* out, int T, long long out_size) {
    if (threadIdx.x == 0) {
        int off = 0;
        for (int e = 0; e < NE; e++) { g_off[e] = off; off += g_cnt[e]; }
        float aux = 0.0f;
        for (int e = 0; e < NE; e++)
            aux += (g_imp[e] / (float)T) * ((float)g_cnt[e] / (float)(T * 2));
        aux *= (float)NE;
        long long oi = (long long)T * D_MODEL;
        if (oi < out_size) out[oi] = aux;
    }
}

// ======================= 3xFP16 mma grouped GEMMs ==========================
// CTA tile 128(M) x 128(N), K-chunk 16, double-buffered cp.async.
// A smem: [128 rows][AST=24] fp32  (float2 fragment loads conflict-free)
// B smem: [16 k][BST=132] fp32     (2tig-row fragment loads conflict-free)
#define AST 24
#define BST 132

struct __align__(16) SmemMMA {
    float A[2][128 * AST];   // 2 * 12288 B
    float B[2][16 * BST];    // 2 * 8448 B
    int   stok[128];
    float swt[128];
};

template<int LDK>
__device__ __forceinline__ void load_chunk(SmemMMA& sm, int buf, int k0,
                                           const float* __restrict__ src_rows_base,
                                           const int* __restrict__ srow,
                                           const float* __restrict__ Wb, int WLD, int n0,
                                           int tid) {
    uint32_t aBase = smem_u32(sm.A[buf]);
    uint32_t bBase = smem_u32(sm.B[buf]);
    // A: 128 rows x 4 float4
#pragma unroll
    for (int it = 0; it < 2; it++) {
        int i = tid + it * 256;
        int row = i >> 2, c = i & 3;
        const float* g = src_rows_base + (size_t)srow[row] * LDK + k0 + c * 4;
        cp16(aBase + (row * AST + c * 4) * 4, g);
    }
    // B: 16 k-rows x 32 float4
#pragma unroll
    for (int it = 0; it < 2; it++) {
        int i = tid + it * 256;
        int kr = i >> 5, f4 = i & 31;
        const float* g = Wb + (size_t)(k0 + kr) * WLD + n0 + f4 * 4;
        cp16(bBase + (kr * BST + f4 * 4) * 4, g);
    }
}

// one K-chunk (full k16), 3xFP16 compensated: 48 MMAs
__device__ __forceinline__ void compute_chunk(const SmemMMA& sm, int buf,
                                              int warp_m, int warp_n, int g, int tig,
                                              float acc[2][8][4]) {
    const float* Ab = sm.A[buf];
    const float* Bb = sm.B[buf];

    uint32_t ah[2][4], al[2][4];
#pragma unroll
    for (int mt = 0; mt < 2; mt++) {
        const float* p = Ab + (warp_m + mt * 16 + g) * AST;
        float2 v0 = *(const float2*)(p + 2 * tig);              // row g,   k=2t..2t+1
        float2 v1 = *(const float2*)(p + 8 * AST + 2 * tig);    // row g+8
        float2 v2 = *(const float2*)(p + 2 * tig + 8);          // row g,   k=2t+8..9
        float2 v3 = *(const float2*)(p + 8 * AST + 2 * tig + 8);
        split2(v0.x, v0.y, ah[mt][0], al[mt][0]);
        split2(v1.x, v1.y, ah[mt][1], al[mt][1]);
        split2(v2.x, v2.y, ah[mt][2], al[mt][2]);
        split2(v3.x, v3.y, ah[mt][3], al[mt][3]);
    }
    uint32_t bh[8][2], bl[8][2];
#pragma unroll
    for (int nt = 0; nt < 8; nt++) {
        int n = warp_n + nt * 8 + g;
        float u0 = Bb[(2 * tig) * BST + n];
        float u1 = Bb[(2 * tig + 1) * BST + n];
        float u2 = Bb[(2 * tig + 8) * BST + n];
        float u3 = Bb[(2 * tig + 9) * BST + n];
        split2(u0, u1, bh[nt][0], bl[nt][0]);
        split2(u2, u3, bh[nt][1], bl[nt][1]);
    }
#pragma unroll
    for (int mt = 0; mt < 2; mt++)
#pragma unroll
        for (int nt = 0; nt < 8; nt++) {
            mma_f16(acc[mt][nt], ah[mt][0], ah[mt][1], ah[mt][2], ah[mt][3],
                    bl[nt][0], bl[nt][1]);
            mma_f16(acc[mt][nt], al[mt][0], al[mt][1], al[mt][2], al[mt][3],
                    bh[nt][0], bh[nt][1]);
            mma_f16(acc[mt][nt], ah[mt][0], ah[mt][1], ah[mt][2], ah[mt][3],
                    bh[nt][0], bh[nt][1]);
        }
}

// GEMM1: H[off+m, n] = gelu(x[tok_m] . W1[e][:, n] + b1[e][n])
__global__ void __launch_bounds__(256, 2) gemm1_mma(const float* __restrict__ x,
                                                    const float* __restrict__ W1,
                                                    const float* __restrict__ b1) {
    __shared__ SmemMMA sm;
    const int e = blockIdx.z;
    const int cnt = g_cnt[e];
    const int m0 = blockIdx.y * 128;
    if (m0 >= cnt) return;
    const int n0 = blockIdx.x * 128;
    const int tid = threadIdx.x;
    const int wid = tid >> 5, lid = tid & 31;
    const int g = lid >> 2, tig = lid & 3;
    const int warp_m = (wid & 3) * 32, warp_n = (wid >> 2) * 64;

    if (tid < 128) sm.stok[tid] = g_tok[e * CAP + min(m0 + tid, cnt - 1)];
    __syncthreads();

    const float* Wb = W1 + (size_t)e * D_MODEL * D_FF;
    float acc[2][8][4];
#pragma unroll
    for (int a = 0; a < 2; a++)
#pragma unroll
        for (int b = 0; b < 8; b++)
#pragma unroll
            for (int c = 0; c < 4; c++) acc[a][b][c] = 0.0f;

    const int NC = D_MODEL / 16;  // 64
    load_chunk<D_MODEL>(sm, 0, 0, x, sm.stok, Wb, D_FF, n0, tid);
    CP_COMMIT();
    for (int c = 0; c < NC; c++) {
        if (c + 1 < NC) {
            load_chunk<D_MODEL>(sm, (c + 1) & 1, (c + 1) * 16, x, sm.stok, Wb, D_FF, n0, tid);
            CP_COMMIT();
            CP_WAIT(1);
        } else {
            CP_WAIT(0);
        }
        __syncthreads();
        compute_chunk(sm, c & 1, warp_m, warp_n, g, tig, acc);
        __syncthreads();
    }

    const int base = g_off[e];
#pragma unroll
    for (int mt = 0; mt < 2; mt++) {
#pragma unroll
        for (int half = 0; half < 2; half++) {
            int m = m0 + warp_m + mt * 16 + g + half * 8;
            if (m < cnt) {
                float* hrow = g_H + (size_t)(base + m) * D_FF;
#pragma unroll
                for (int nt = 0; nt < 8; nt++) {
                    int col = n0 + warp_n + nt * 8 + 2 * tig;
                    float v0 = acc[mt][nt][half * 2 + 0] + b1[e * D_FF + col];
                    float v1 = acc[mt][nt][half * 2 + 1] + b1[e * D_FF + col + 1];
                    float2 o;
                    o.x = 0.5f * v0 * (1.0f + erff(v0 * 0.70710678118654752f));
                    o.y = 0.5f * v1 * (1.0f + erff(v1 * 0.70710678118654752f));
                    *(float2*)(hrow + col) = o;
                }
            }
        }
    }
}

// GEMM2: out[tok_m, n] += w_m * (H[base+m, :] . W2[e][:, n] + b2[e][n])
__global__ void __launch_bounds__(256, 2) gemm2_mma(const float* __restrict__ W2,
                                                    const float* __restrict__ b2,
                                                    float* __restrict__ out) {
    __shared__ SmemMMA sm;
    __shared__ int srow[128];
    const int e = blockIdx.z;
    const int cnt = g_cnt[e];
    const int m0 = blockIdx.y * 128;
    if (m0 >= cnt) return;
    const int n0 = blockIdx.x * 128;
    const int tid = threadIdx.x;
    const int wid = tid >> 5, lid = tid & 31;
    const int g = lid >> 2, tig = lid & 3;
    const int warp_m = (wid & 3) * 32, warp_n = (wid >> 2) * 64;
    const int base = g_off[e];

    if (tid < 128) {
        int m = min(m0 + tid, cnt - 1);
        sm.stok[tid] = g_tok[e * CAP + m];
        sm.swt[tid]  = g_wt[e * CAP + m];
        srow[tid]    = base + m;
    }
    __syncthreads();

    const float* Wb = W2 + (size_t)e * D_FF * D_MODEL;
    float acc[2][8][4];
#pragma unroll
    for (int a = 0; a < 2; a++)
#pragma unroll
        for (int b = 0; b < 8; b++)
#pragma unroll
            for (int c = 0; c < 4; c++) acc[a][b][c] = 0.0f;

    const int NC = D_FF / 16;  // 128
    load_chunk<D_FF>(sm, 0, 0, g_H, srow, Wb, D_MODEL, n0, tid);
    CP_COMMIT();
    for (int c = 0; c < NC; c++) {
        if (c + 1 < NC) {
            load_chunk<D_FF>(sm, (c + 1) & 1, (c + 1) * 16, g_H, srow, Wb, D_MODEL, n0, tid);
            CP_COMMIT();
            CP_WAIT(1);
        } else {
            CP_WAIT(0);
        }
        __syncthreads();
        compute_chunk(sm, c & 1, warp_m, warp_n, g, tig, acc);
        __syncthreads();
    }

#pragma unroll
    for (int mt = 0; mt < 2; mt++) {
#pragma unroll
        for (int half = 0; half < 2; half++) {
            int ml = warp_m + mt * 16 + g + half * 8;
            int m = m0 + ml;
            if (m < cnt) {
                int tok = sm.stok[ml];
                float w = sm.swt[ml];
                float* orow = out + (size_t)tok * D_MODEL;
#pragma unroll
                for (int nt = 0; nt < 8; nt++) {
                    int col = n0 + warp_n + nt * 8 + 2 * tig;
                    float y0 = acc[mt][nt][half * 2 + 0] + b2[e * D_MODEL + col];
                    float y1 = acc[mt][nt][half * 2 + 1] + b2[e * D_MODEL + col + 1];
                    atomicAdd(&orow[col], w * y0);
                    atomicAdd(&orow[col + 1], w * y1);
                }
            }
        }
    }
}

// ===========================================================================
extern "C" void kernel_launch(void* const* d_in, const int* in_sizes, int n_in,
                              void* d_out, int out_size) {
    const float* x  = (const float*)d_in[0];
    const float* rw = (const float*)d_in[1];
    const float* rb = (const float*)d_in[2];
    const float* W1 = (const float*)d_in[3];
    const float* b1 = (const float*)d_in[4];
    const float* W2 = (const float*)d_in[5];
    const float* b2 = (const float*)d_in[6];
    float* out = (float*)d_out;

    const int T = in_sizes[0] / D_MODEL;

    zero_kernel<<<(out_size + 255) / 256, 256>>>(out, out_size);
    router_kernel<<<T, 256>>>(x, rw, rb);
    finalize_kernel<<<1, 1>>>(out, T, (long long)out_size);

    dim3 g1(D_FF / 128, (T + 127) / 128, NE);
    gemm1_mma<<<g1, 256>>>(x, W1, b1);

    dim3 g2(D_MODEL / 128, (T + 127) / 128, NE);
    gemm2_mma<<<g2, 256>>>(W2, b2, out);
}

// round 9
// speedup vs baseline: 2.5043x; 1.0442x over previous
#include <cuda_runtime.h>
#include <cuda_fp16.h>
#include <cstdint>
#include <math.h>

#define D_MODEL 1024
#define D_FF    2048
#define NE      8
#define CAP     4096
#define MAXT    4096

// ---- device scratch ----
__device__ float g_H[2 * MAXT * D_FF];   // 64 MB
__device__ __align__(16) __half g_W1hi[NE * D_FF * D_MODEL];   // [e][n][k]
__device__ __align__(16) __half g_W1lo[NE * D_FF * D_MODEL];
__device__ __align__(16) __half g_W2hi[NE * D_MODEL * D_FF];   // [e][n][k]
__device__ __align__(16) __half g_W2lo[NE * D_MODEL * D_FF];
__device__ int   g_tok[NE * CAP];
__device__ float g_wt[NE * CAP];
__device__ int   g_cnt[NE];
__device__ int   g_off[NE];
__device__ float g_imp[NE];

// ======================= portable PTX helpers ==============================
__device__ __forceinline__ uint32_t smem_u32(const void* p) {
    uint32_t a;
    asm("{ .reg .u64 t; cvta.to.shared.u64 t, %1; cvt.u32.u64 %0, t; }" : "=r"(a) : "l"(p));
    return a;
}
__device__ __forceinline__ void cp16(uint32_t smem, const void* g) {
    asm volatile("cp.async.cg.shared.global [%0], [%1], 16;" :: "r"(smem), "l"(g));
}
#define CP_COMMIT() asm volatile("cp.async.commit_group;" ::: "memory")
#define CP_WAIT(n)  asm volatile("cp.async.wait_group %0;" :: "n"(n) : "memory")

__device__ __forceinline__ void mma_f16(float* c,
                                        uint32_t a0, uint32_t a1, uint32_t a2, uint32_t a3,
                                        uint32_t b0, uint32_t b1) {
    asm volatile(
        "mma.sync.aligned.m16n8k16.row.col.f32.f16.f16.f32 "
        "{%0,%1,%2,%3}, {%4,%5,%6,%7}, {%8,%9}, {%0,%1,%2,%3};"
        : "+f"(c[0]), "+f"(c[1]), "+f"(c[2]), "+f"(c[3])
        : "r"(a0), "r"(a1), "r"(a2), "r"(a3), "r"(b0), "r"(b1));
}

// fp16 2-way split of a float pair, packed into hi/lo __half2 bit-patterns
__device__ __forceinline__ void split2(float v0, float v1, uint32_t& hi, uint32_t& lo) {
    __half2 h2 = __floats2half2_rn(v0, v1);
    float2 hf = __half22float2(h2);
    __half2 l2 = __floats2half2_rn(v0 - hf.x, v1 - hf.y);
    hi = *reinterpret_cast<uint32_t*>(&h2);
    lo = *reinterpret_cast<uint32_t*>(&l2);
}
__device__ __forceinline__ void hsplit(float v, __half& h, __half& l) {
    h = __float2half(v);
    l = __float2half(v - __half2float(h));
}

// ======================= prep: W[e][K][N] fp32 -> hi/lo [e][N][K] fp16 =====
// NOTE: output symbols referenced from DEVICE code (host-side symbol-decay of
// __device__ arrays is the bug that killed R5/R6/R8).
template<int K, int N>
__device__ __forceinline__ void split_w_body(const float* __restrict__ W,
                                             __half* __restrict__ Whi,
                                             __half* __restrict__ Wlo) {
    __shared__ float tile[32][33];
    const int e = blockIdx.z;
    const int k0 = blockIdx.y * 32, n0 = blockIdx.x * 32;
    const int tx = threadIdx.x, ty = threadIdx.y;   // 32 x 8
    const float* Wb = W + (size_t)e * K * N;
#pragma unroll
    for (int r = 0; r < 4; r++)
        tile[ty + r * 8][tx] = Wb[(size_t)(k0 + ty + r * 8) * N + n0 + tx];
    __syncthreads();
    __half* oh = Whi + (size_t)e * K * N;
    __half* ol = Wlo + (size_t)e * K * N;
#pragma unroll
    for (int r = 0; r < 4; r++) {
        int n = n0 + ty + r * 8;
        float v = tile[tx][ty + r * 8];
        __half h, l;
        hsplit(v, h, l);
        oh[(size_t)n * K + k0 + tx] = h;
        ol[(size_t)n * K + k0 + tx] = l;
    }
}
__global__ void split_w1_kernel(const float* __restrict__ W) {
    split_w_body<D_MODEL, D_FF>(W, g_W1hi, g_W1lo);
}
__global__ void split_w2_kernel(const float* __restrict__ W) {
    split_w_body<D_FF, D_MODEL>(W, g_W2hi, g_W2lo);
}

// ======================= small kernels =====================================
__global__ void zero_kernel(float* out, int n) {
    int i = blockIdx.x * blockDim.x + threadIdx.x;
    if (i < n) out[i] = 0.0f;
    if (blockIdx.x == 0 && threadIdx.x < NE) { g_cnt[threadIdx.x] = 0; g_imp[threadIdx.x] = 0.0f; }
}

__global__ void router_kernel(const float* __restrict__ x,
                              const float* __restrict__ rw,
                              const float* __restrict__ rb) {
    const int t = blockIdx.x, tid = threadIdx.x;
    float part[NE];
#pragma unroll
    for (int e = 0; e < NE; e++) part[e] = 0.0f;
    const float* xr = x + (size_t)t * D_MODEL;
    for (int d = tid; d < D_MODEL; d += 256) {
        float xv = xr[d];
        const float4* w4 = (const float4*)(rw + (size_t)d * NE);
        float4 w0 = w4[0], w1 = w4[1];
        part[0] += xv * w0.x; part[1] += xv * w0.y; part[2] += xv * w0.z; part[3] += xv * w0.w;
        part[4] += xv * w1.x; part[5] += xv * w1.y; part[6] += xv * w1.z; part[7] += xv * w1.w;
    }
#pragma unroll
    for (int e = 0; e < NE; e++)
#pragma unroll
        for (int o = 16; o > 0; o >>= 1) part[e] += __shfl_down_sync(0xffffffffu, part[e], o);
    __shared__ float sred[8][NE];
    const int wid = tid >> 5, lid = tid & 31;
    if (lid == 0)
#pragma unroll
        for (int e = 0; e < NE; e++) sred[wid][e] = part[e];
    __syncthreads();
    if (tid == 0) {
        float lg[NE];
#pragma unroll
        for (int e = 0; e < NE; e++) {
            float s = rb[e];
#pragma unroll
            for (int w = 0; w < 8; w++) s += sred[w][e];
            lg[e] = s;
        }
        float m = lg[0];
#pragma unroll
        for (int e = 1; e < NE; e++) m = fmaxf(m, lg[e]);
        float p[NE], s = 0.0f;
#pragma unroll
        for (int e = 0; e < NE; e++) { p[e] = expf(lg[e] - m); s += p[e]; }
        float inv = 1.0f / s;
#pragma unroll
        for (int e = 0; e < NE; e++) { p[e] *= inv; atomicAdd(&g_imp[e], p[e]); }
        int i0 = 0;
#pragma unroll
        for (int e = 1; e < NE; e++) if (p[e] > p[i0]) i0 = e;
        int i1 = (i0 == 0) ? 1 : 0;
#pragma unroll
        for (int e = 0; e < NE; e++) if (e != i0 && p[e] > p[i1]) i1 = e;
        float ps = fmaxf(p[i0] + p[i1], 1e-9f);
        int s0 = atomicAdd(&g_cnt[i0], 1);
        g_tok[i0 * CAP + s0] = t; g_wt[i0 * CAP + s0] = p[i0] / ps;
        int s1 = atomicAdd(&g_cnt[i1], 1);
        g_tok[i1 * CAP + s1] = t; g_wt[i1 * CAP + s1] = p[i1] / ps;
    }
}

__global__ void finalize_kernel(float* out, int T, long long out_size) {
    if (threadIdx.x == 0) {
        int off = 0;
        for (int e = 0; e < NE; e++) { g_off[e] = off; off += g_cnt[e]; }
        float aux = 0.0f;
        for (int e = 0; e < NE; e++)
            aux += (g_imp[e] / (float)T) * ((float)g_cnt[e] / (float)(T * 2));
        aux *= (float)NE;
        long long oi = (long long)T * D_MODEL;
        if (oi < out_size) out[oi] = aux;
    }
}

// ======================= 3xFP16 mma grouped GEMMs ==========================
// CTA tile 128(M) x 128(N), K-chunk 16, double-buffered cp.async.
// A smem: [128 rows][AST=24] fp32 (float2 fragment loads conflict-free)
// B smem: hi/lo fp16 planes [128 n][16 k], 32B/row, 16B blocks XOR-swizzled:
//   phys_block = c ^ ((n>>2)&1)  -> conflict-free fragment LDS.
#define AST 24
#define BPL (128 * 16)

struct __align__(16) SmemMMA {
    float  A[2][128 * AST];        // 24576 B
    __half Bh[2][BPL], Bl[2][BPL]; // 16384 B
    int   stok[128];
    float swt[128];
};

template<int LDK>
__device__ __forceinline__ void load_chunk(SmemMMA& sm, int buf, int k0,
                                           const float* __restrict__ src_rows_base,
                                           const int* __restrict__ srow,
                                           const __half* __restrict__ Wh,
                                           const __half* __restrict__ Wl,
                                           int LDKB, int n0, int tid) {
    uint32_t aBase = smem_u32(sm.A[buf]);
    uint32_t bhB = smem_u32(sm.Bh[buf]);
    uint32_t blB = smem_u32(sm.Bl[buf]);
    // A: 128 rows x 4 float4 (fp32)
#pragma unroll
    for (int it = 0; it < 2; it++) {
        int i = tid + it * 256;
        int row = i >> 2, c = i & 3;
        const float* g = src_rows_base + (size_t)srow[row] * LDK + k0 + c * 4;
        cp16(aBase + (row * AST + c * 4) * 4, g);
    }
    // B: 128 n-rows x {hi,lo} x 2 k-halves (fp16), XOR-swizzled 16B blocks
#pragma unroll
    for (int it = 0; it < 2; it++) {
        int i = tid + it * 256;
        int row = i >> 2, sub = i & 3;
        int pl = sub >> 1, c = sub & 1;
        int phys = c ^ ((row >> 2) & 1);
        uint32_t dst = (pl ? blB : bhB) + row * 32 + phys * 16;
        const __half* src = (pl ? Wl : Wh) + (size_t)(n0 + row) * LDKB + k0 + c * 8;
        cp16(dst, src);
    }
}

// one K-chunk (full k16), 3xFP16 compensated: 48 MMAs, A split in-register
__device__ __forceinline__ void compute_chunk(const SmemMMA& sm, int buf,
                                              int warp_m, int warp_n, int g, int tig,
                                              float acc[2][8][4]) {
    const float* Ab = sm.A[buf];
    const __half* Bhp = sm.Bh[buf];
    const __half* Blp = sm.Bl[buf];

    uint32_t ah[2][4], al[2][4];
#pragma unroll
    for (int mt = 0; mt < 2; mt++) {
        const float* p = Ab + (warp_m + mt * 16 + g) * AST;
        float2 v0 = *(const float2*)(p + 2 * tig);
        float2 v1 = *(const float2*)(p + 8 * AST + 2 * tig);
        float2 v2 = *(const float2*)(p + 2 * tig + 8);
        float2 v3 = *(const float2*)(p + 8 * AST + 2 * tig + 8);
        split2(v0.x, v0.y, ah[mt][0], al[mt][0]);
        split2(v1.x, v1.y, ah[mt][1], al[mt][1]);
        split2(v2.x, v2.y, ah[mt][2], al[mt][2]);
        split2(v3.x, v3.y, ah[mt][3], al[mt][3]);
    }
    const int sw = (g >> 2) & 1;
    const int o0 = sw * 8 + 2 * tig;        // k block 0 (swizzled)
    const int o1 = (sw ^ 1) * 8 + 2 * tig;  // k block 1
    uint32_t bh[8][2], bl[8][2];
#pragma unroll
    for (int nt = 0; nt < 8; nt++) {
        int nb = (warp_n + nt * 8 + g) * 16;
        bh[nt][0] = *(const uint32_t*)(Bhp + nb + o0);
        bh[nt][1] = *(const uint32_t*)(Bhp + nb + o1);
        bl[nt][0] = *(const uint32_t*)(Blp + nb + o0);
        bl[nt][1] = *(const uint32_t*)(Blp + nb + o1);
    }
#pragma unroll
    for (int mt = 0; mt < 2; mt++)
#pragma unroll
        for (int nt = 0; nt < 8; nt++) {
            mma_f16(acc[mt][nt], ah[mt][0], ah[mt][1], ah[mt][2], ah[mt][3],
                    bl[nt][0], bl[nt][1]);
            mma_f16(acc[mt][nt], al[mt][0], al[mt][1], al[mt][2], al[mt][3],
                    bh[nt][0], bh[nt][1]);
            mma_f16(acc[mt][nt], ah[mt][0], ah[mt][1], ah[mt][2], ah[mt][3],
                    bh[nt][0], bh[nt][1]);
        }
}

// GEMM1: H[off+m, n] = gelu(x[tok_m] . W1[e][:, n] + b1[e][n])
__global__ void __launch_bounds__(256, 2) gemm1_mma(const float* __restrict__ x,
                                                    const float* __restrict__ b1) {
    __shared__ SmemMMA sm;
    const int e = blockIdx.z;
    const int cnt = g_cnt[e];
    const int m0 = blockIdx.y * 128;
    if (m0 >= cnt) return;
    const int n0 = blockIdx.x * 128;
    const int tid = threadIdx.x;
    const int wid = tid >> 5, lid = tid & 31;
    const int g = lid >> 2, tig = lid & 3;
    const int warp_m = (wid & 3) * 32, warp_n = (wid >> 2) * 64;

    if (tid < 128) sm.stok[tid] = g_tok[e * CAP + min(m0 + tid, cnt - 1)];
    __syncthreads();

    const __half* Wh = g_W1hi + (size_t)e * D_FF * D_MODEL;
    const __half* Wl = g_W1lo + (size_t)e * D_FF * D_MODEL;
    float acc[2][8][4];
#pragma unroll
    for (int a = 0; a < 2; a++)
#pragma unroll
        for (int b = 0; b < 8; b++)
#pragma unroll
            for (int c = 0; c < 4; c++) acc[a][b][c] = 0.0f;

    const int NC = D_MODEL / 16;  // 64
    load_chunk<D_MODEL>(sm, 0, 0, x, sm.stok, Wh, Wl, D_MODEL, n0, tid);
    CP_COMMIT();
    for (int c = 0; c < NC; c++) {
        if (c + 1 < NC) {
            load_chunk<D_MODEL>(sm, (c + 1) & 1, (c + 1) * 16, x, sm.stok, Wh, Wl, D_MODEL, n0, tid);
            CP_COMMIT();
            CP_WAIT(1);
        } else {
            CP_WAIT(0);
        }
        __syncthreads();
        compute_chunk(sm, c & 1, warp_m, warp_n, g, tig, acc);
        __syncthreads();
    }

    const int base = g_off[e];
#pragma unroll
    for (int mt = 0; mt < 2; mt++) {
#pragma unroll
        for (int half = 0; half < 2; half++) {
            int m = m0 + warp_m + mt * 16 + g + half * 8;
            if (m < cnt) {
                float* hrow = g_H + (size_t)(base + m) * D_FF;
#pragma unroll
                for (int nt = 0; nt < 8; nt++) {
                    int col = n0 + warp_n + nt * 8 + 2 * tig;
                    float v0 = acc[mt][nt][half * 2 + 0] + b1[e * D_FF + col];
                    float v1 = acc[mt][nt][half * 2 + 1] + b1[e * D_FF + col + 1];
                    float2 o;
                    o.x = 0.5f * v0 * (1.0f + erff(v0 * 0.70710678118654752f));
                    o.y = 0.5f * v1 * (1.0f + erff(v1 * 0.70710678118654752f));
                    *(float2*)(hrow + col) = o;
                }
            }
        }
    }
}

// GEMM2: out[tok_m, n] += w_m * (H[base+m, :] . W2[e][:, n] + b2[e][n])
__global__ void __launch_bounds__(256, 2) gemm2_mma(const float* __restrict__ b2,
                                                    float* __restrict__ out) {
    __shared__ SmemMMA sm;
    __shared__ int srow[128];
    const int e = blockIdx.z;
    const int cnt = g_cnt[e];
    const int m0 = blockIdx.y * 128;
    if (m0 >= cnt) return;
    const int n0 = blockIdx.x * 128;
    const int tid = threadIdx.x;
    const int wid = tid >> 5, lid = tid & 31;
    const int g = lid >> 2, tig = lid & 3;
    const int warp_m = (wid & 3) * 32, warp_n = (wid >> 2) * 64;
    const int base = g_off[e];

    if (tid < 128) {
        int m = min(m0 + tid, cnt - 1);
        sm.stok[tid] = g_tok[e * CAP + m];
        sm.swt[tid]  = g_wt[e * CAP + m];
        srow[tid]    = base + m;
    }
    __syncthreads();

    const __half* Wh = g_W2hi + (size_t)e * D_MODEL * D_FF;
    const __half* Wl = g_W2lo + (size_t)e * D_MODEL * D_FF;
    float acc[2][8][4];
#pragma unroll
    for (int a = 0; a < 2; a++)
#pragma unroll
        for (int b = 0; b < 8; b++)
#pragma unroll
            for (int c = 0; c < 4; c++) acc[a][b][c] = 0.0f;

    const int NC = D_FF / 16;  // 128
    load_chunk<D_FF>(sm, 0, 0, g_H, srow, Wh, Wl, D_FF, n0, tid);
    CP_COMMIT();
    for (int c = 0; c < NC; c++) {
        if (c + 1 < NC) {
            load_chunk<D_FF>(sm, (c + 1) & 1, (c + 1) * 16, g_H, srow, Wh, Wl, D_FF, n0, tid);
            CP_COMMIT();
            CP_WAIT(1);
        } else {
            CP_WAIT(0);
        }
        __syncthreads();
        compute_chunk(sm, c & 1, warp_m, warp_n, g, tig, acc);
        __syncthreads();
    }

#pragma unroll
    for (int mt = 0; mt < 2; mt++) {
#pragma unroll
        for (int half = 0; half < 2; half++) {
            int ml = warp_m + mt * 16 + g + half * 8;
            int m = m0 + ml;
            if (m < cnt) {
                int tok = sm.stok[ml];
                float w = sm.swt[ml];
                float* orow = out + (size_t)tok * D_MODEL;
#pragma unroll
                for (int nt = 0; nt < 8; nt++) {
                    int col = n0 + warp_n + nt * 8 + 2 * tig;
                    float y0 = acc[mt][nt][half * 2 + 0] + b2[e * D_MODEL + col];
                    float y1 = acc[mt][nt][half * 2 + 1] + b2[e * D_MODEL + col + 1];
                    atomicAdd(&orow[col], w * y0);
                    atomicAdd(&orow[col + 1], w * y1);
                }
            }
        }
    }
}

// ===========================================================================
extern "C" void kernel_launch(void* const* d_in, const int* in_sizes, int n_in,
                              void* d_out, int out_size) {
    const float* x  = (const float*)d_in[0];
    const float* rw = (const float*)d_in[1];
    const float* rb = (const float*)d_in[2];
    const float* W1 = (const float*)d_in[3];
    const float* b1 = (const float*)d_in[4];
    const float* W2 = (const float*)d_in[5];
    const float* b2 = (const float*)d_in[6];
    float* out = (float*)d_out;

    const int T = in_sizes[0] / D_MODEL;

    zero_kernel<<<(out_size + 255) / 256, 256>>>(out, out_size);
    {
        dim3 blk(32, 8);
        dim3 gw1(D_FF / 32, D_MODEL / 32, NE);
        split_w1_kernel<<<gw1, blk>>>(W1);
        dim3 gw2(D_MODEL / 32, D_FF / 32, NE);
        split_w2_kernel<<<gw2, blk>>>(W2);
    }
    router_kernel<<<T, 256>>>(x, rw, rb);
    finalize_kernel<<<1, 1>>>(out, T, (long long)out_size);

    dim3 g1(D_FF / 128, (T + 127) / 128, NE);
    gemm1_mma<<<g1, 256>>>(x, b1);

    dim3 g2(D_MODEL / 128, (T + 127) / 128, NE);
    gemm2_mma<<<g2, 256>>>(b2, out);
}